// round 1
// baseline (speedup 1.0000x reference)
#include <cuda_runtime.h>
#include <cstdint>

#define T_DIM 256
#define C_DIM 128
#define L_DIM 48
#define DEPTH 8          // prefetch pipeline depth == normalization period

// One warp per batch element. lane handles extended states s = 4*lane + j, j=0..3.
// S = 2*L+1 = 97 states: lanes 0..23 fully valid, lane 24 only j=0 (s=96), lanes 25..31 idle.
// Linear-space CTC forward with 128x prescale and warp-sum renormalization every DEPTH steps.
__global__ __launch_bounds__(32)
void ctc_fwd_kernel(const float* __restrict__ y,      // [B, T, C] softmax probs
                    const int*   __restrict__ labels, // [B, L]
                    float*       __restrict__ out)    // [B]
{
    const int b    = blockIdx.x;
    const int lane = threadIdx.x;

    const float* yb = y + (size_t)b * (T_DIM * C_DIM);
    const int*   lb = labels + (size_t)b * L_DIM;

    // --- per-lane static state: classes + skip masks + validity ---
    const bool lv = (lane < 24);                  // has label states (s = 4l+1, 4l+3 < 97)
    int cls0 = 127, cls1 = 127, clsm1 = -1;
    if (lv) { cls0 = lb[2 * lane]; cls1 = lb[2 * lane + 1]; }
    if (lane >= 1 && lane < 24) clsm1 = lb[2 * lane - 1];

    // can_skip: only odd s>=3, requires label != previous label
    const float m1 = (lane >= 1 && lv && cls0 != clsm1) ? 1.0f : 0.0f; // s = 4l+1
    const float m3 = (lv && cls1 != cls0)               ? 1.0f : 0.0f; // s = 4l+3

    const bool v0 = (lane <= 24);                 // s = 4l   < 97
    const bool v1 = lv, v2 = lv, v3 = lv;         // s = 4l+1/2/3 < 97

    // p_scaled = (p + 1e-7) * 128 = fmaf(p, 128, 1.28e-5)
    const float SC = 128.0f, EB = 1.28e-5f;

    // --- init alpha at t=0: alpha[0]=p(blank), alpha[1]=p(label0), else 0 ---
    float pb0 = __ldg(yb + 127);
    float pl0 = __ldg(yb + cls0);
    float a0 = (lane == 0) ? fmaf(pb0, SC, EB) : 0.0f;
    float a1 = (lane == 0) ? fmaf(pl0, SC, EB) : 0.0f;
    float a2 = 0.0f, a3 = 0.0f;

    // --- prefetch pipeline for t = 1..DEPTH ---
    float bpb[DEPTH], bq0[DEPTH], bq1[DEPTH];
#pragma unroll
    for (int d = 0; d < DEPTH; d++) {
        const float* row = yb + (size_t)(1 + d) * C_DIM;
        bpb[d] = __ldg(row + 127);
        bq0[d] = __ldg(row + cls0);
        bq1[d] = __ldg(row + cls1);
    }

    float acc = 0.0f;   // accumulated log of normalization constants

    for (int tb = 1; tb < T_DIM; tb += DEPTH) {
#pragma unroll
        for (int d = 0; d < DEPTH; d++) {
            const int t = tb + d;
            if (t < T_DIM) {
                const float pb = bpb[d], q0 = bq0[d], q1 = bq1[d];
                const float pcb  = v0 ? fmaf(pb, SC, EB) : 0.0f;  // blank, s=4l
                const float pcb2 = v2 ? fmaf(pb, SC, EB) : 0.0f;  // blank, s=4l+2
                const float pc1  = v1 ? fmaf(q0, SC, EB) : 0.0f;
                const float pc3  = v3 ? fmaf(q1, SC, EB) : 0.0f;

                float up3 = __shfl_up_sync(0xffffffffu, a3, 1);   // alpha[4l-1]
                float up2 = __shfl_up_sync(0xffffffffu, a2, 1);   // alpha[4l-2]
                if (lane == 0) { up3 = 0.0f; up2 = 0.0f; }

                const float n0 = (a0 + up3)                 * pcb;   // s even: no skip
                const float n1 = fmaf(m1, up2, a1 + a0)     * pc1;   // wait: s-2 of 4l+1 is 4l-1 = up3
                const float n1x = n1; (void)n1x;
                // correct forms:
                const float c1 = fmaf(m1, up3, a1 + a0)     * pc1;   // s=4l+1: s-1=a0, s-2=up3
                const float c2 = (a2 + a1)                  * pcb2;  // s=4l+2
                const float c3 = fmaf(m3, a1, a3 + a2)      * pc3;   // s=4l+3: s-1=a2, s-2=a1

                a0 = n0; a1 = c1; a2 = c2; a3 = c3;

                const int tn = t + DEPTH;                  // prefetch ahead
                if (tn < T_DIM) {
                    const float* row = yb + (size_t)tn * C_DIM;
                    bpb[d] = __ldg(row + 127);
                    bq0[d] = __ldg(row + cls0);
                    bq1[d] = __ldg(row + cls1);
                }
            }
        }
        // renormalize (linear recurrence => scaling commutes; fold into acc)
        float s = (a0 + a1) + (a2 + a3);
#pragma unroll
        for (int o = 16; o; o >>= 1) s += __shfl_xor_sync(0xffffffffu, s, o);
        acc += __logf(s);
        const float inv = __frcp_rn(s);
        a0 *= inv; a1 *= inv; a2 *= inv; a3 *= inv;
    }

    // loss = -( log(alpha[95] + alpha[96]) + acc - T*log(128) )
    const float v95 = __shfl_sync(0xffffffffu, a3, 23);  // s = 4*23+3 = 95
    const float v96 = __shfl_sync(0xffffffffu, a0, 24);  // s = 4*24   = 96
    if (lane == 0) {
        // 256 * log(128) = 1792 * ln2
        const float offs = 1242.11974756972f;
        out[b] = offs - acc - __logf(v95 + v96);
    }
}

extern "C" void kernel_launch(void* const* d_in, const int* in_sizes, int n_in,
                              void* d_out, int out_size)
{
    const float* y      = (const float*)d_in[0];   // [B, T, C] float32
    const int*   labels = (const int*)d_in[1];     // [B, L] int32
    float*       out    = (float*)d_out;           // [B, 1] float32
    const int B = in_sizes[1] / L_DIM;
    ctc_fwd_kernel<<<B, 32>>>(y, labels, out);
}